// round 4
// baseline (speedup 1.0000x reference)
#include <cuda_runtime.h>
#include <math.h>

#define N 8192
#define D 64
#define EPS 0.1f
#define INV_EPS 10.0f

#define TM 128
#define TN 128
#define SROW 132   // padded smem row stride (floats), keeps float4 alignment, breaks conflicts

// Scratch (device globals — no allocation allowed)
__device__ float g_K[(size_t)N * (size_t)N];   // 256 MB kernel matrix
__device__ float g_spn[N];
__device__ float g_sqn[N];
__device__ float g_u[N];
__device__ float g_v[N];
__device__ float g_part[N];

// ---------------------------------------------------------------------------
// Row norms of P and Q: one warp per row (64 floats = 32 float2 per row)
// ---------------------------------------------------------------------------
__global__ void norms_kernel(const float* __restrict__ P, const float* __restrict__ Q) {
    int w = (blockIdx.x * blockDim.x + threadIdx.x) >> 5;
    int lane = threadIdx.x & 31;
    if (w >= N) return;
    float2 p = reinterpret_cast<const float2*>(P)[w * 32 + lane];
    float s = p.x * p.x + p.y * p.y;
    float2 q = reinterpret_cast<const float2*>(Q)[w * 32 + lane];
    float t = q.x * q.x + q.y * q.y;
    #pragma unroll
    for (int o = 16; o > 0; o >>= 1) {
        s += __shfl_xor_sync(0xffffffffu, s, o);
        t += __shfl_xor_sync(0xffffffffu, t, o);
    }
    if (lane == 0) { g_spn[w] = s; g_sqn[w] = t; }
}

__global__ void init_kernel() {
    int i = blockIdx.x * blockDim.x + threadIdx.x;
    if (i < N) g_u[i] = 1.0f / (float)D;
}

// ---------------------------------------------------------------------------
// Build K = exp(-sqrt(max(|p|^2+|q|^2-2 p.q, 0))/EPS)
// Tiled 128x128 fp32 GEMM, 8x8 micro-tile per thread, k-major smem tiles
// (transposed on store so the compute loop does conflict-free LDS.128).
// ---------------------------------------------------------------------------
extern __shared__ float smem_dyn[];

__global__ void build_kernel(const float* __restrict__ P, const float* __restrict__ Q) {
    float* As = smem_dyn;                  // [D][SROW]  P-tile, k-major
    float* Bs = smem_dyn + D * SROW;       // [D][SROW]  Q-tile, k-major

    const int tid = threadIdx.x;           // 256 threads
    const int by = blockIdx.y, bx = blockIdx.x;
    const int k0 = (tid & 15) * 4;
    const int r0 = tid >> 4;

    // Load + transpose tiles: each thread loads a float4 along k for 8 rows
    #pragma unroll
    for (int r = r0; r < TM; r += 16) {
        float4 p = reinterpret_cast<const float4*>(P + (size_t)(by * TM + r) * D)[tid & 15];
        As[(k0 + 0) * SROW + r] = p.x;
        As[(k0 + 1) * SROW + r] = p.y;
        As[(k0 + 2) * SROW + r] = p.z;
        As[(k0 + 3) * SROW + r] = p.w;
        float4 q = reinterpret_cast<const float4*>(Q + (size_t)(bx * TN + r) * D)[tid & 15];
        Bs[(k0 + 0) * SROW + r] = q.x;
        Bs[(k0 + 1) * SROW + r] = q.y;
        Bs[(k0 + 2) * SROW + r] = q.z;
        Bs[(k0 + 3) * SROW + r] = q.w;
    }
    __syncthreads();

    const int ty = tid >> 4, tx = tid & 15;
    float acc[8][8];
    #pragma unroll
    for (int i = 0; i < 8; i++)
        #pragma unroll
        for (int j = 0; j < 8; j++) acc[i][j] = 0.0f;

    #pragma unroll 4
    for (int k = 0; k < D; k++) {
        float a[8], b[8];
        *reinterpret_cast<float4*>(&a[0]) = *reinterpret_cast<float4*>(&As[k * SROW + ty * 8]);
        *reinterpret_cast<float4*>(&a[4]) = *reinterpret_cast<float4*>(&As[k * SROW + ty * 8 + 4]);
        *reinterpret_cast<float4*>(&b[0]) = *reinterpret_cast<float4*>(&Bs[k * SROW + tx * 8]);
        *reinterpret_cast<float4*>(&b[4]) = *reinterpret_cast<float4*>(&Bs[k * SROW + tx * 8 + 4]);
        #pragma unroll
        for (int i = 0; i < 8; i++)
            #pragma unroll
            for (int j = 0; j < 8; j++)
                acc[i][j] = fmaf(a[i], b[j], acc[i][j]);
    }

    float sp[8], sq[8];
    #pragma unroll
    for (int i = 0; i < 8; i++) sp[i] = g_spn[by * TM + ty * 8 + i];
    #pragma unroll
    for (int j = 0; j < 8; j++) sq[j] = g_sqn[bx * TN + tx * 8 + j];

    #pragma unroll
    for (int i = 0; i < 8; i++) {
        float out[8];
        #pragma unroll
        for (int j = 0; j < 8; j++) {
            float d = sp[i] + sq[j] - 2.0f * acc[i][j];
            float c = sqrtf(fmaxf(d, 0.0f));
            out[j] = __expf(-c * INV_EPS);
        }
        size_t base = (size_t)(by * TM + ty * 8 + i) * N + (size_t)(bx * TN + tx * 8);
        *reinterpret_cast<float4*>(&g_K[base])     = make_float4(out[0], out[1], out[2], out[3]);
        *reinterpret_cast<float4*>(&g_K[base + 4]) = make_float4(out[4], out[5], out[6], out[7]);
    }
}

// ---------------------------------------------------------------------------
// y = 1 / (K @ x).  One block per row, streaming the 32KB row as float4.
// dir=0: x=u, y=v.  dir=1: x=v, y=u.
// ---------------------------------------------------------------------------
__global__ void matvec_kernel(int dir) {
    const float* __restrict__ x = dir ? g_v : g_u;
    float* __restrict__ y = dir ? g_u : g_v;
    const int row = blockIdx.x;
    const float4* __restrict__ Kr = reinterpret_cast<const float4*>(g_K + (size_t)row * N);
    const float4* __restrict__ xv = reinterpret_cast<const float4*>(x);

    float acc = 0.0f;
    #pragma unroll 8
    for (int j = threadIdx.x; j < N / 4; j += 256) {
        float4 kk = Kr[j];
        float4 xx = xv[j];
        acc += kk.x * xx.x + kk.y * xx.y + kk.z * xx.z + kk.w * xx.w;
    }

    __shared__ float sm[8];
    #pragma unroll
    for (int o = 16; o > 0; o >>= 1) acc += __shfl_xor_sync(0xffffffffu, acc, o);
    if ((threadIdx.x & 31) == 0) sm[threadIdx.x >> 5] = acc;
    __syncthreads();
    if (threadIdx.x == 0) {
        float total = 0.0f;
        #pragma unroll
        for (int w = 0; w < 8; w++) total += sm[w];
        y[row] = 1.0f / total;
    }
}

// ---------------------------------------------------------------------------
// Fused last matvec + loss row-partials.
//   s_i = sum_j K_ij v_j            (gives final u_i = 1/s_i)
//   t_i = sum_j K_ij v_j * C_ij     with C_ij = -EPS * ln(K_ij)
//   g_part[i] = t_i / s_i
// ---------------------------------------------------------------------------
__global__ void final_kernel() {
    const int row = blockIdx.x;
    const float4* __restrict__ Kr = reinterpret_cast<const float4*>(g_K + (size_t)row * N);
    const float4* __restrict__ vv = reinterpret_cast<const float4*>(g_v);

    float s = 0.0f, t = 0.0f;
    #pragma unroll 4
    for (int j = threadIdx.x; j < N / 4; j += 256) {
        float4 kk = Kr[j];
        float4 xx = vv[j];
        {
            float kv = kk.x * xx.x; s += kv;
            if (kk.x > 0.0f) t += kv * (-EPS * __logf(kk.x));
        }
        {
            float kv = kk.y * xx.y; s += kv;
            if (kk.y > 0.0f) t += kv * (-EPS * __logf(kk.y));
        }
        {
            float kv = kk.z * xx.z; s += kv;
            if (kk.z > 0.0f) t += kv * (-EPS * __logf(kk.z));
        }
        {
            float kv = kk.w * xx.w; s += kv;
            if (kk.w > 0.0f) t += kv * (-EPS * __logf(kk.w));
        }
    }

    __shared__ float sms[8], smt[8];
    #pragma unroll
    for (int o = 16; o > 0; o >>= 1) {
        s += __shfl_xor_sync(0xffffffffu, s, o);
        t += __shfl_xor_sync(0xffffffffu, t, o);
    }
    if ((threadIdx.x & 31) == 0) { sms[threadIdx.x >> 5] = s; smt[threadIdx.x >> 5] = t; }
    __syncthreads();
    if (threadIdx.x == 0) {
        float st = 0.0f, tt = 0.0f;
        #pragma unroll
        for (int w = 0; w < 8; w++) { st += sms[w]; tt += smt[w]; }
        g_part[row] = tt / st;
    }
}

__global__ void sum_kernel(float* __restrict__ out) {
    float a = 0.0f;
    for (int i = threadIdx.x; i < N; i += 1024) a += g_part[i];
    __shared__ float sm[32];
    #pragma unroll
    for (int o = 16; o > 0; o >>= 1) a += __shfl_xor_sync(0xffffffffu, a, o);
    if ((threadIdx.x & 31) == 0) sm[threadIdx.x >> 5] = a;
    __syncthreads();
    if (threadIdx.x == 0) {
        float total = 0.0f;
        #pragma unroll
        for (int w = 0; w < 32; w++) total += sm[w];
        out[0] = total;
    }
}

// ---------------------------------------------------------------------------
extern "C" void kernel_launch(void* const* d_in, const int* in_sizes, int n_in,
                              void* d_out, int out_size) {
    (void)in_sizes; (void)n_in; (void)out_size;
    const float* P = (const float*)d_in[0];
    const float* Q = (const float*)d_in[1];
    float* out = (float*)d_out;

    const int smem_bytes = 2 * D * SROW * (int)sizeof(float);   // 67584 B
    cudaFuncSetAttribute(build_kernel, cudaFuncAttributeMaxDynamicSharedMemorySize, smem_bytes);

    norms_kernel<<<N / 8, 256>>>(P, Q);
    init_kernel<<<N / 256, 256>>>();
    build_kernel<<<dim3(N / TN, N / TM), 256, smem_bytes>>>(P, Q);

    for (int it = 0; it < 5; it++) {
        matvec_kernel<<<N, 256>>>(0);            // v = 1/(K u)
        if (it < 4) matvec_kernel<<<N, 256>>>(1); // u = 1/(K v)
    }
    final_kernel<<<N, 256>>>();                   // fused 10th matvec + plan*C partials
    sum_kernel<<<1, 1024>>>(out);
}

// round 7
// speedup vs baseline: 1.2129x; 1.2129x over previous
#include <cuda_runtime.h>
#include <cuda_fp16.h>
#include <math.h>

#define N 8192
#define D 64
#define EPS 0.1f
#define INV_EPS 10.0f

#define TM 128
#define TN 128
#define SROW 132   // padded smem row stride (floats), float4-aligned, conflict-free

// Scratch (device globals — no allocation allowed)
__device__ __half g_K[(size_t)N * (size_t)N];   // 128 MB kernel matrix (fp16)
__device__ float g_spn[N];
__device__ float g_sqn[N];
__device__ float g_u[N];
__device__ float g_v[N];
__device__ float g_part[N];

// ---------------------------------------------------------------------------
// Row norms of P and Q + init of u: one warp per row
// ---------------------------------------------------------------------------
__global__ void norms_kernel(const float* __restrict__ P, const float* __restrict__ Q) {
    int w = (blockIdx.x * blockDim.x + threadIdx.x) >> 5;
    int lane = threadIdx.x & 31;
    if (w >= N) return;
    float2 p = reinterpret_cast<const float2*>(P)[w * 32 + lane];
    float s = p.x * p.x + p.y * p.y;
    float2 q = reinterpret_cast<const float2*>(Q)[w * 32 + lane];
    float t = q.x * q.x + q.y * q.y;
    #pragma unroll
    for (int o = 16; o > 0; o >>= 1) {
        s += __shfl_xor_sync(0xffffffffu, s, o);
        t += __shfl_xor_sync(0xffffffffu, t, o);
    }
    if (lane == 0) {
        g_spn[w] = s;
        g_sqn[w] = t;
        g_u[w] = 1.0f / (float)D;
    }
}

// ---------------------------------------------------------------------------
// Build K = exp(-sqrt(max(|p|^2+|q|^2-2 p.q, 0))/EPS), stored fp16.
// Tiled 128x128 fp32 GEMM, 8x8 micro-tile, k-major smem tiles.
// ---------------------------------------------------------------------------
extern __shared__ float smem_dyn[];

__global__ void build_kernel(const float* __restrict__ P, const float* __restrict__ Q) {
    float* As = smem_dyn;                  // [D][SROW]  P-tile, k-major
    float* Bs = smem_dyn + D * SROW;       // [D][SROW]  Q-tile, k-major

    const int tid = threadIdx.x;           // 256 threads
    const int by = blockIdx.y, bx = blockIdx.x;
    const int k0 = (tid & 15) * 4;
    const int r0 = tid >> 4;

    #pragma unroll
    for (int r = r0; r < TM; r += 16) {
        float4 p = reinterpret_cast<const float4*>(P + (size_t)(by * TM + r) * D)[tid & 15];
        As[(k0 + 0) * SROW + r] = p.x;
        As[(k0 + 1) * SROW + r] = p.y;
        As[(k0 + 2) * SROW + r] = p.z;
        As[(k0 + 3) * SROW + r] = p.w;
        float4 q = reinterpret_cast<const float4*>(Q + (size_t)(bx * TN + r) * D)[tid & 15];
        Bs[(k0 + 0) * SROW + r] = q.x;
        Bs[(k0 + 1) * SROW + r] = q.y;
        Bs[(k0 + 2) * SROW + r] = q.z;
        Bs[(k0 + 3) * SROW + r] = q.w;
    }
    __syncthreads();

    const int ty = tid >> 4, tx = tid & 15;
    float acc[8][8];
    #pragma unroll
    for (int i = 0; i < 8; i++)
        #pragma unroll
        for (int j = 0; j < 8; j++) acc[i][j] = 0.0f;

    #pragma unroll 4
    for (int k = 0; k < D; k++) {
        float a[8], b[8];
        *reinterpret_cast<float4*>(&a[0]) = *reinterpret_cast<float4*>(&As[k * SROW + ty * 8]);
        *reinterpret_cast<float4*>(&a[4]) = *reinterpret_cast<float4*>(&As[k * SROW + ty * 8 + 4]);
        *reinterpret_cast<float4*>(&b[0]) = *reinterpret_cast<float4*>(&Bs[k * SROW + tx * 8]);
        *reinterpret_cast<float4*>(&b[4]) = *reinterpret_cast<float4*>(&Bs[k * SROW + tx * 8 + 4]);
        #pragma unroll
        for (int i = 0; i < 8; i++)
            #pragma unroll
            for (int j = 0; j < 8; j++)
                acc[i][j] = fmaf(a[i], b[j], acc[i][j]);
    }

    float sp[8], sq[8];
    #pragma unroll
    for (int i = 0; i < 8; i++) sp[i] = g_spn[by * TM + ty * 8 + i];
    #pragma unroll
    for (int j = 0; j < 8; j++) sq[j] = g_sqn[bx * TN + tx * 8 + j];

    #pragma unroll
    for (int i = 0; i < 8; i++) {
        __half2 out[4];
        #pragma unroll
        for (int j = 0; j < 4; j++) {
            float d0 = sp[i] + sq[2 * j]     - 2.0f * acc[i][2 * j];
            float d1 = sp[i] + sq[2 * j + 1] - 2.0f * acc[i][2 * j + 1];
            float c0 = sqrtf(fmaxf(d0, 0.0f));
            float c1 = sqrtf(fmaxf(d1, 0.0f));
            out[j] = __floats2half2_rn(__expf(-c0 * INV_EPS), __expf(-c1 * INV_EPS));
        }
        size_t base = (size_t)(by * TM + ty * 8 + i) * N + (size_t)(bx * TN + tx * 8);
        *reinterpret_cast<uint4*>(&g_K[base]) = *reinterpret_cast<uint4*>(out);
    }
}

// ---------------------------------------------------------------------------
// y = 1 / (K @ x).  One block per row, streaming the 16KB fp16 row as uint4
// (8 halves per load). dir=0: x=u, y=v.  dir=1: x=v, y=u.
// ---------------------------------------------------------------------------
__global__ void matvec_kernel(int dir) {
    const float* __restrict__ x = dir ? g_v : g_u;
    float* __restrict__ y = dir ? g_u : g_v;
    const int row = blockIdx.x;
    const uint4* __restrict__ Kr = reinterpret_cast<const uint4*>(g_K + (size_t)row * N);
    const float4* __restrict__ xv = reinterpret_cast<const float4*>(x);

    float acc = 0.0f;
    #pragma unroll 4
    for (int j = threadIdx.x; j < N / 8; j += 256) {
        uint4 raw = Kr[j];
        float2 k0 = __half22float2(*reinterpret_cast<__half2*>(&raw.x));
        float2 k1 = __half22float2(*reinterpret_cast<__half2*>(&raw.y));
        float2 k2 = __half22float2(*reinterpret_cast<__half2*>(&raw.z));
        float2 k3 = __half22float2(*reinterpret_cast<__half2*>(&raw.w));
        float4 x0 = xv[2 * j];
        float4 x1 = xv[2 * j + 1];
        acc += k0.x * x0.x + k0.y * x0.y + k1.x * x0.z + k1.y * x0.w;
        acc += k2.x * x1.x + k2.y * x1.y + k3.x * x1.z + k3.y * x1.w;
    }

    __shared__ float sm[8];
    #pragma unroll
    for (int o = 16; o > 0; o >>= 1) acc += __shfl_xor_sync(0xffffffffu, acc, o);
    if ((threadIdx.x & 31) == 0) sm[threadIdx.x >> 5] = acc;
    __syncthreads();
    if (threadIdx.x == 0) {
        float total = 0.0f;
        #pragma unroll
        for (int w = 0; w < 8; w++) total += sm[w];
        y[row] = 1.0f / total;
    }
}

// ---------------------------------------------------------------------------
// Fused last matvec + loss row-partials.
//   s_i = sum_j K_ij v_j,  t_i = sum_j K_ij v_j * C_ij,  C_ij = -EPS*ln(K_ij)
//   g_part[i] = t_i / s_i
// ---------------------------------------------------------------------------
__global__ void final_kernel() {
    const int row = blockIdx.x;
    const uint4* __restrict__ Kr = reinterpret_cast<const uint4*>(g_K + (size_t)row * N);
    const float4* __restrict__ vv = reinterpret_cast<const float4*>(g_v);

    float s = 0.0f, t = 0.0f;
    #pragma unroll 2
    for (int j = threadIdx.x; j < N / 8; j += 256) {
        uint4 raw = Kr[j];
        float2 k0 = __half22float2(*reinterpret_cast<__half2*>(&raw.x));
        float2 k1 = __half22float2(*reinterpret_cast<__half2*>(&raw.y));
        float2 k2 = __half22float2(*reinterpret_cast<__half2*>(&raw.z));
        float2 k3 = __half22float2(*reinterpret_cast<__half2*>(&raw.w));
        float4 x0 = vv[2 * j];
        float4 x1 = vv[2 * j + 1];
        float kf[8] = {k0.x, k0.y, k1.x, k1.y, k2.x, k2.y, k3.x, k3.y};
        float xf[8] = {x0.x, x0.y, x0.z, x0.w, x1.x, x1.y, x1.z, x1.w};
        #pragma unroll
        for (int e = 0; e < 8; e++) {
            float kv = kf[e] * xf[e];
            s += kv;
            // if kf==0, kv==0 and 0 * finite = 0 (log of clamped arg is finite)
            t += kv * (-EPS * __logf(fmaxf(kf[e], 1e-30f)));
        }
    }

    __shared__ float sms[8], smt[8];
    #pragma unroll
    for (int o = 16; o > 0; o >>= 1) {
        s += __shfl_xor_sync(0xffffffffu, s, o);
        t += __shfl_xor_sync(0xffffffffu, t, o);
    }
    if ((threadIdx.x & 31) == 0) { sms[threadIdx.x >> 5] = s; smt[threadIdx.x >> 5] = t; }
    __syncthreads();
    if (threadIdx.x == 0) {
        float st = 0.0f, tt = 0.0f;
        #pragma unroll
        for (int w = 0; w < 8; w++) { st += sms[w]; tt += smt[w]; }
        g_part[row] = tt / st;
    }
}

__global__ void sum_kernel(float* __restrict__ out) {
    float a = 0.0f;
    for (int i = threadIdx.x; i < N; i += 1024) a += g_part[i];
    __shared__ float sm[32];
    #pragma unroll
    for (int o = 16; o > 0; o >>= 1) a += __shfl_xor_sync(0xffffffffu, a, o);
    if ((threadIdx.x & 31) == 0) sm[threadIdx.x >> 5] = a;
    __syncthreads();
    if (threadIdx.x == 0) {
        float total = 0.0f;
        #pragma unroll
        for (int w = 0; w < 32; w++) total += sm[w];
        out[0] = total;
    }
}

// ---------------------------------------------------------------------------
extern "C" void kernel_launch(void* const* d_in, const int* in_sizes, int n_in,
                              void* d_out, int out_size) {
    (void)in_sizes; (void)n_in; (void)out_size;
    const float* P = (const float*)d_in[0];
    const float* Q = (const float*)d_in[1];
    float* out = (float*)d_out;

    const int smem_bytes = 2 * D * SROW * (int)sizeof(float);   // 67584 B
    cudaFuncSetAttribute(build_kernel, cudaFuncAttributeMaxDynamicSharedMemorySize, smem_bytes);

    norms_kernel<<<N / 8, 256>>>(P, Q);
    build_kernel<<<dim3(N / TN, N / TM), 256, smem_bytes>>>(P, Q);

    for (int it = 0; it < 5; it++) {
        matvec_kernel<<<N, 256>>>(0);             // v = 1/(K u)
        if (it < 4) matvec_kernel<<<N, 256>>>(1); // u = 1/(K v)
    }
    final_kernel<<<N, 256>>>();                   // fused 10th matvec + plan*C partials
    sum_kernel<<<1, 1024>>>(out);
}

// round 8
// speedup vs baseline: 1.3053x; 1.0762x over previous
#include <cuda_runtime.h>
#include <cuda_fp16.h>
#include <math.h>

#define N 8192
#define D 64
#define EPS 0.1f
#define INV_EPS 10.0f

#define TM 128
#define TN 128
#define SROW 132   // padded smem row stride (floats), float4-aligned, conflict-free

typedef unsigned long long u64;

// packed f32x2 helpers (sm_103a dual-lane fp32)
__device__ __forceinline__ u64 splat2(float a) {
    u64 d;
    asm("mov.b64 %0, {%1, %1};" : "=l"(d) : "r"(__float_as_uint(a)));
    return d;
}
__device__ __forceinline__ void fma2(u64& d, u64 a, u64 b) {
    asm("fma.rn.f32x2 %0, %1, %2, %0;" : "+l"(d) : "l"(a), "l"(b));
}
__device__ __forceinline__ void unpack2(u64 v, float& lo, float& hi) {
    unsigned int l, h;
    asm("mov.b64 {%0, %1}, %2;" : "=r"(l), "=r"(h) : "l"(v));
    lo = __uint_as_float(l);
    hi = __uint_as_float(h);
}

// Scratch (device globals — no allocation allowed)
__device__ __half g_K[(size_t)N * (size_t)N];   // 128 MB kernel matrix (fp16)
__device__ float g_spn[N];
__device__ float g_sqn[N];
__device__ float g_u[N];
__device__ float g_v[N];
__device__ float g_part[N];

// ---------------------------------------------------------------------------
// Row norms of P and Q + init of u: one warp per row
// ---------------------------------------------------------------------------
__global__ void norms_kernel(const float* __restrict__ P, const float* __restrict__ Q) {
    int w = (blockIdx.x * blockDim.x + threadIdx.x) >> 5;
    int lane = threadIdx.x & 31;
    if (w >= N) return;
    float2 p = reinterpret_cast<const float2*>(P)[w * 32 + lane];
    float s = p.x * p.x + p.y * p.y;
    float2 q = reinterpret_cast<const float2*>(Q)[w * 32 + lane];
    float t = q.x * q.x + q.y * q.y;
    #pragma unroll
    for (int o = 16; o > 0; o >>= 1) {
        s += __shfl_xor_sync(0xffffffffu, s, o);
        t += __shfl_xor_sync(0xffffffffu, t, o);
    }
    if (lane == 0) {
        g_spn[w] = s;
        g_sqn[w] = t;
        g_u[w] = 1.0f / (float)D;
    }
}

// ---------------------------------------------------------------------------
// Build K = exp(-sqrt(max(|p|^2+|q|^2-2 p.q, 0))/EPS), stored fp16.
// Tiled 128x128 GEMM with packed fma.rn.f32x2 (j-pairs), 8x8 micro-tile.
// ---------------------------------------------------------------------------
extern __shared__ float smem_dyn[];

__global__ void __launch_bounds__(256)
build_kernel(const float* __restrict__ P, const float* __restrict__ Q) {
    float* As = smem_dyn;                  // [D][SROW]  P-tile, k-major
    float* Bs = smem_dyn + D * SROW;       // [D][SROW]  Q-tile, k-major

    const int tid = threadIdx.x;           // 256 threads
    const int by = blockIdx.y, bx = blockIdx.x;
    const int k0 = (tid & 15) * 4;
    const int r0 = tid >> 4;

    #pragma unroll
    for (int r = r0; r < TM; r += 16) {
        float4 p = reinterpret_cast<const float4*>(P + (size_t)(by * TM + r) * D)[tid & 15];
        As[(k0 + 0) * SROW + r] = p.x;
        As[(k0 + 1) * SROW + r] = p.y;
        As[(k0 + 2) * SROW + r] = p.z;
        As[(k0 + 3) * SROW + r] = p.w;
        float4 q = reinterpret_cast<const float4*>(Q + (size_t)(bx * TN + r) * D)[tid & 15];
        Bs[(k0 + 0) * SROW + r] = q.x;
        Bs[(k0 + 1) * SROW + r] = q.y;
        Bs[(k0 + 2) * SROW + r] = q.z;
        Bs[(k0 + 3) * SROW + r] = q.w;
    }
    __syncthreads();

    const int ty = tid >> 4, tx = tid & 15;

    u64 acc2[8][4];   // [i][j-pair], packed {j=2*jp, j=2*jp+1}
    #pragma unroll
    for (int i = 0; i < 8; i++)
        #pragma unroll
        for (int jp = 0; jp < 4; jp++) acc2[i][jp] = 0ull;

    #pragma unroll 2
    for (int k = 0; k < D; k++) {
        float a[8];
        *reinterpret_cast<float4*>(&a[0]) = *reinterpret_cast<float4*>(&As[k * SROW + ty * 8]);
        *reinterpret_cast<float4*>(&a[4]) = *reinterpret_cast<float4*>(&As[k * SROW + ty * 8 + 4]);
        // b pairs loaded directly as 64-bit (8-byte aligned: k*528 + tx*32)
        const u64* bp = reinterpret_cast<const u64*>(&Bs[k * SROW + tx * 8]);
        u64 bv[4];
        #pragma unroll
        for (int jp = 0; jp < 4; jp++) bv[jp] = bp[jp];
        u64 av[8];
        #pragma unroll
        for (int i = 0; i < 8; i++) av[i] = splat2(a[i]);
        #pragma unroll
        for (int i = 0; i < 8; i++)
            #pragma unroll
            for (int jp = 0; jp < 4; jp++)
                fma2(acc2[i][jp], av[i], bv[jp]);
    }

    float sp[8], sq[8];
    #pragma unroll
    for (int i = 0; i < 8; i++) sp[i] = g_spn[by * TM + ty * 8 + i];
    #pragma unroll
    for (int j = 0; j < 8; j++) sq[j] = g_sqn[bx * TN + tx * 8 + j];

    #pragma unroll
    for (int i = 0; i < 8; i++) {
        __half2 out[4];
        #pragma unroll
        for (int jp = 0; jp < 4; jp++) {
            float dot0, dot1;
            unpack2(acc2[i][jp], dot0, dot1);
            float d0 = sp[i] + sq[2 * jp]     - 2.0f * dot0;
            float d1 = sp[i] + sq[2 * jp + 1] - 2.0f * dot1;
            float c0 = sqrtf(fmaxf(d0, 0.0f));
            float c1 = sqrtf(fmaxf(d1, 0.0f));
            out[jp] = __floats2half2_rn(__expf(-c0 * INV_EPS), __expf(-c1 * INV_EPS));
        }
        size_t base = (size_t)(by * TM + ty * 8 + i) * N + (size_t)(bx * TN + tx * 8);
        *reinterpret_cast<uint4*>(&g_K[base]) = *reinterpret_cast<uint4*>(out);
    }
}

// ---------------------------------------------------------------------------
// y = 1 / (K @ x).  4 rows per block, x cached in smem (keeps the fp32 x
// loads off the L1tex wavefront path), 4 independent K-row loads per step.
// dir=0: x=u, y=v.  dir=1: x=v, y=u.
// ---------------------------------------------------------------------------
#define RPB 4

__global__ void __launch_bounds__(256) matvec_kernel(int dir) {
    const float* __restrict__ x = dir ? g_v : g_u;
    float* __restrict__ y = dir ? g_u : g_v;

    __shared__ float xs[N];          // 32 KB
    __shared__ float red[RPB][8];

    const int tid = threadIdx.x;
    #pragma unroll
    for (int i = 0; i < N / 4 / 256; i++)
        reinterpret_cast<float4*>(xs)[i * 256 + tid] =
            reinterpret_cast<const float4*>(x)[i * 256 + tid];
    __syncthreads();

    const int row0 = blockIdx.x * RPB;
    float acc[RPB] = {0.0f, 0.0f, 0.0f, 0.0f};

    #pragma unroll
    for (int it = 0; it < N / 8 / 256; it++) {         // 4 iterations
        const int j = it * 256 + tid;                  // uint4 index (8 halves)
        uint4 raw[RPB];
        #pragma unroll
        for (int r = 0; r < RPB; r++)
            raw[r] = reinterpret_cast<const uint4*>(g_K + (size_t)(row0 + r) * N)[j];
        float xf[8];
        *reinterpret_cast<float4*>(&xf[0]) = *reinterpret_cast<float4*>(&xs[j * 8]);
        *reinterpret_cast<float4*>(&xf[4]) = *reinterpret_cast<float4*>(&xs[j * 8 + 4]);
        #pragma unroll
        for (int r = 0; r < RPB; r++) {
            const __half2* h = reinterpret_cast<const __half2*>(&raw[r]);
            #pragma unroll
            for (int e = 0; e < 4; e++) {
                float2 kk = __half22float2(h[e]);
                acc[r] += kk.x * xf[2 * e] + kk.y * xf[2 * e + 1];
            }
        }
    }

    const int lane = tid & 31, wid = tid >> 5;
    #pragma unroll
    for (int r = 0; r < RPB; r++) {
        float a = acc[r];
        #pragma unroll
        for (int o = 16; o > 0; o >>= 1) a += __shfl_xor_sync(0xffffffffu, a, o);
        if (lane == 0) red[r][wid] = a;
    }
    __syncthreads();
    if (tid < RPB) {
        float total = 0.0f;
        #pragma unroll
        for (int w = 0; w < 8; w++) total += red[tid][w];
        y[row0 + tid] = 1.0f / total;
    }
}

// ---------------------------------------------------------------------------
// Fused last matvec + loss row-partials, same 4-rows-per-block structure.
//   s_i = sum_j K_ij v_j,  t_i = sum_j K_ij v_j * C_ij,  C_ij = -EPS*ln(K_ij)
//   g_part[i] = t_i / s_i
// ---------------------------------------------------------------------------
__global__ void __launch_bounds__(256) final_kernel() {
    __shared__ float xs[N];
    __shared__ float reds[RPB][8], redt[RPB][8];

    const int tid = threadIdx.x;
    #pragma unroll
    for (int i = 0; i < N / 4 / 256; i++)
        reinterpret_cast<float4*>(xs)[i * 256 + tid] =
            reinterpret_cast<const float4*>(g_v)[i * 256 + tid];
    __syncthreads();

    const int row0 = blockIdx.x * RPB;
    float s[RPB] = {0.0f, 0.0f, 0.0f, 0.0f};
    float t[RPB] = {0.0f, 0.0f, 0.0f, 0.0f};

    #pragma unroll
    for (int it = 0; it < N / 8 / 256; it++) {
        const int j = it * 256 + tid;
        uint4 raw[RPB];
        #pragma unroll
        for (int r = 0; r < RPB; r++)
            raw[r] = reinterpret_cast<const uint4*>(g_K + (size_t)(row0 + r) * N)[j];
        float xf[8];
        *reinterpret_cast<float4*>(&xf[0]) = *reinterpret_cast<float4*>(&xs[j * 8]);
        *reinterpret_cast<float4*>(&xf[4]) = *reinterpret_cast<float4*>(&xs[j * 8 + 4]);
        #pragma unroll
        for (int r = 0; r < RPB; r++) {
            const __half2* h = reinterpret_cast<const __half2*>(&raw[r]);
            #pragma unroll
            for (int e = 0; e < 4; e++) {
                float2 kk = __half22float2(h[e]);
                float kv0 = kk.x * xf[2 * e];
                float kv1 = kk.y * xf[2 * e + 1];
                s[r] += kv0 + kv1;
                t[r] += kv0 * (-EPS * __logf(fmaxf(kk.x, 1e-30f)))
                      + kv1 * (-EPS * __logf(fmaxf(kk.y, 1e-30f)));
            }
        }
    }

    const int lane = tid & 31, wid = tid >> 5;
    #pragma unroll
    for (int r = 0; r < RPB; r++) {
        float a = s[r], b = t[r];
        #pragma unroll
        for (int o = 16; o > 0; o >>= 1) {
            a += __shfl_xor_sync(0xffffffffu, a, o);
            b += __shfl_xor_sync(0xffffffffu, b, o);
        }
        if (lane == 0) { reds[r][wid] = a; redt[r][wid] = b; }
    }
    __syncthreads();
    if (tid < RPB) {
        float st = 0.0f, tt = 0.0f;
        #pragma unroll
        for (int w = 0; w < 8; w++) { st += reds[tid][w]; tt += redt[tid][w]; }
        g_part[row0 + tid] = tt / st;
    }
}

__global__ void sum_kernel(float* __restrict__ out) {
    float a = 0.0f;
    for (int i = threadIdx.x; i < N; i += 1024) a += g_part[i];
    __shared__ float sm[32];
    #pragma unroll
    for (int o = 16; o > 0; o >>= 1) a += __shfl_xor_sync(0xffffffffu, a, o);
    if ((threadIdx.x & 31) == 0) sm[threadIdx.x >> 5] = a;
    __syncthreads();
    if (threadIdx.x == 0) {
        float total = 0.0f;
        #pragma unroll
        for (int w = 0; w < 32; w++) total += sm[w];
        out[0] = total;
    }
}

// ---------------------------------------------------------------------------
extern "C" void kernel_launch(void* const* d_in, const int* in_sizes, int n_in,
                              void* d_out, int out_size) {
    (void)in_sizes; (void)n_in; (void)out_size;
    const float* P = (const float*)d_in[0];
    const float* Q = (const float*)d_in[1];
    float* out = (float*)d_out;

    const int smem_bytes = 2 * D * SROW * (int)sizeof(float);   // 67584 B
    cudaFuncSetAttribute(build_kernel, cudaFuncAttributeMaxDynamicSharedMemorySize, smem_bytes);

    norms_kernel<<<N / 8, 256>>>(P, Q);
    build_kernel<<<dim3(N / TN, N / TM), 256, smem_bytes>>>(P, Q);

    for (int it = 0; it < 5; it++) {
        matvec_kernel<<<N / RPB, 256>>>(0);             // v = 1/(K u)
        if (it < 4) matvec_kernel<<<N / RPB, 256>>>(1); // u = 1/(K v)
    }
    final_kernel<<<N / RPB, 256>>>();                   // fused 10th matvec + partials
    sum_kernel<<<1, 1024>>>(out);
}

// round 10
// speedup vs baseline: 1.7115x; 1.3112x over previous
#include <cuda_runtime.h>
#include <cuda_fp16.h>
#include <cuda_bf16.h>
#include <math.h>
#include <stdint.h>

#define N 8192
#define D 64
#define EPS 0.1f
#define INV_EPS 10.0f

// Scratch (device globals — no allocation allowed)
__device__ __half g_K[(size_t)N * (size_t)N];   // 128 MB kernel matrix (fp16)
__device__ float g_spn[N];
__device__ float g_sqn[N];
__device__ float g_u[N];
__device__ float g_v[N];
__device__ float g_part[N];

__device__ __forceinline__ float sqrt_approx(float x) {
    float r;
    asm("sqrt.approx.f32 %0, %1;" : "=f"(r) : "f"(x));
    return r;
}

// m16n8k16 bf16 HMMA (sm_80+, valid on base sm_103 target)
__device__ __forceinline__ void mma16816(float* d, const uint32_t* a, const uint32_t* b) {
    asm volatile(
        "mma.sync.aligned.m16n8k16.row.col.f32.bf16.bf16.f32 "
        "{%0,%1,%2,%3}, {%4,%5,%6,%7}, {%8,%9}, {%0,%1,%2,%3};"
        : "+f"(d[0]), "+f"(d[1]), "+f"(d[2]), "+f"(d[3])
        : "r"(a[0]), "r"(a[1]), "r"(a[2]), "r"(a[3]), "r"(b[0]), "r"(b[1]));
}

// ---------------------------------------------------------------------------
// Row norms of P and Q + init of u: one warp per row
// ---------------------------------------------------------------------------
__global__ void norms_kernel(const float* __restrict__ P, const float* __restrict__ Q) {
    int w = (blockIdx.x * blockDim.x + threadIdx.x) >> 5;
    int lane = threadIdx.x & 31;
    if (w >= N) return;
    float2 p = reinterpret_cast<const float2*>(P)[w * 32 + lane];
    float s = p.x * p.x + p.y * p.y;
    float2 q = reinterpret_cast<const float2*>(Q)[w * 32 + lane];
    float t = q.x * q.x + q.y * q.y;
    #pragma unroll
    for (int o = 16; o > 0; o >>= 1) {
        s += __shfl_xor_sync(0xffffffffu, s, o);
        t += __shfl_xor_sync(0xffffffffu, t, o);
    }
    if (lane == 0) {
        g_spn[w] = s;
        g_sqn[w] = t;
        g_u[w] = 1.0f / (float)D;
    }
}

// ---------------------------------------------------------------------------
// Build K = exp(-sqrt(max(|p|^2+|q|^2-2 p.q, 0))/EPS) via mma.sync bf16.
// 128x128 tile per CTA, 256 threads = 8 warps, warp tile 64x32 (4x4 mma grid).
// A/B staged bf16 in smem (stride 72 halves -> conflict-free fragment loads).
// Epilogue stages fp16 results in smem (stride 136 halves), then STG.128.
// ---------------------------------------------------------------------------
#define AST 72     // A/B smem stride in halves (144 B)
#define CST 136    // C smem stride in halves  (272 B)

__global__ void __launch_bounds__(256)
build_kernel(const float* __restrict__ P, const float* __restrict__ Q) {
    __shared__ float s_norm[256];                       // sp[0:128], sq[128:256]
    __shared__ __align__(16) char s_tile[2 * 128 * AST * 2];   // 36864 B

    __nv_bfloat16* s_A = reinterpret_cast<__nv_bfloat16*>(s_tile);
    __nv_bfloat16* s_B = s_A + 128 * AST;

    const int tid = threadIdx.x;
    const int by = blockIdx.y, bx = blockIdx.x;

    // Stage norms
    if (tid < 128) s_norm[tid] = g_spn[by * 128 + tid];
    else           s_norm[tid] = g_sqn[bx * 128 + (tid - 128)];

    // Stage P/Q tiles as bf16: thread = (row, half), 32 floats each
    {
        const int row = tid >> 1, half = tid & 1;
        const float4* ps = reinterpret_cast<const float4*>(P + (size_t)(by * 128 + row) * D + half * 32);
        __nv_bfloat16* ad = s_A + row * AST + half * 32;
        #pragma unroll
        for (int s = 0; s < 4; s++) {
            float4 f0 = ps[2 * s], f1 = ps[2 * s + 1];
            __nv_bfloat162 hh[4];
            hh[0] = __floats2bfloat162_rn(f0.x, f0.y);
            hh[1] = __floats2bfloat162_rn(f0.z, f0.w);
            hh[2] = __floats2bfloat162_rn(f1.x, f1.y);
            hh[3] = __floats2bfloat162_rn(f1.z, f1.w);
            *reinterpret_cast<uint4*>(ad + s * 8) = *reinterpret_cast<uint4*>(hh);
        }
        const float4* qs = reinterpret_cast<const float4*>(Q + (size_t)(bx * 128 + row) * D + half * 32);
        __nv_bfloat16* bd = s_B + row * AST + half * 32;
        #pragma unroll
        for (int s = 0; s < 4; s++) {
            float4 f0 = qs[2 * s], f1 = qs[2 * s + 1];
            __nv_bfloat162 hh[4];
            hh[0] = __floats2bfloat162_rn(f0.x, f0.y);
            hh[1] = __floats2bfloat162_rn(f0.z, f0.w);
            hh[2] = __floats2bfloat162_rn(f1.x, f1.y);
            hh[3] = __floats2bfloat162_rn(f1.z, f1.w);
            *reinterpret_cast<uint4*>(bd + s * 8) = *reinterpret_cast<uint4*>(hh);
        }
    }
    __syncthreads();

    const int lane = tid & 31, wid = tid >> 5;
    const int g = lane >> 2, t = lane & 3;
    const int wm = (wid & 1) * 64;        // warp M offset
    const int wn = (wid >> 1) * 32;       // warp N offset

    float acc[4][4][4];
    #pragma unroll
    for (int mi = 0; mi < 4; mi++)
        #pragma unroll
        for (int nj = 0; nj < 4; nj++)
            #pragma unroll
            for (int e = 0; e < 4; e++) acc[mi][nj][e] = 0.0f;

    // K = 64 -> 4 k-steps of 16
    #pragma unroll
    for (int ks = 0; ks < 4; ks++) {
        const int kb = ks * 16 + t * 2;   // half index within row
        uint32_t afr[4][4];
        #pragma unroll
        for (int mi = 0; mi < 4; mi++) {
            const int r = wm + mi * 16 + g;
            afr[mi][0] = *reinterpret_cast<const uint32_t*>(s_A + r * AST + kb);
            afr[mi][1] = *reinterpret_cast<const uint32_t*>(s_A + (r + 8) * AST + kb);
            afr[mi][2] = *reinterpret_cast<const uint32_t*>(s_A + r * AST + kb + 8);
            afr[mi][3] = *reinterpret_cast<const uint32_t*>(s_A + (r + 8) * AST + kb + 8);
        }
        uint32_t bfr[4][2];
        #pragma unroll
        for (int nj = 0; nj < 4; nj++) {
            const int c = wn + nj * 8 + g;
            bfr[nj][0] = *reinterpret_cast<const uint32_t*>(s_B + c * AST + kb);
            bfr[nj][1] = *reinterpret_cast<const uint32_t*>(s_B + c * AST + kb + 8);
        }
        #pragma unroll
        for (int mi = 0; mi < 4; mi++)
            #pragma unroll
            for (int nj = 0; nj < 4; nj++)
                mma16816(acc[mi][nj], afr[mi], bfr[nj]);
    }

    __syncthreads();   // done reading A/B -> safe to overlay C
    __half* Cs = reinterpret_cast<__half*>(s_tile);

    #pragma unroll
    for (int mi = 0; mi < 4; mi++) {
        const int r0 = wm + mi * 16 + g;
        const float spa = s_norm[r0];
        const float spb = s_norm[r0 + 8];
        #pragma unroll
        for (int nj = 0; nj < 4; nj++) {
            const int c0 = wn + nj * 8 + t * 2;
            const float sq0 = s_norm[128 + c0];
            const float sq1 = s_norm[128 + c0 + 1];
            const float* a = acc[mi][nj];
            float e0 = __expf(-INV_EPS * sqrt_approx(fmaxf(spa + sq0 - 2.0f * a[0], 0.0f)));
            float e1 = __expf(-INV_EPS * sqrt_approx(fmaxf(spa + sq1 - 2.0f * a[1], 0.0f)));
            float e2 = __expf(-INV_EPS * sqrt_approx(fmaxf(spb + sq0 - 2.0f * a[2], 0.0f)));
            float e3 = __expf(-INV_EPS * sqrt_approx(fmaxf(spb + sq1 - 2.0f * a[3], 0.0f)));
            __half2 h01 = __floats2half2_rn(e0, e1);
            __half2 h23 = __floats2half2_rn(e2, e3);
            *reinterpret_cast<uint32_t*>(Cs + r0 * CST + c0)       = *reinterpret_cast<uint32_t*>(&h01);
            *reinterpret_cast<uint32_t*>(Cs + (r0 + 8) * CST + c0) = *reinterpret_cast<uint32_t*>(&h23);
        }
    }
    __syncthreads();

    // Coalesced store: 2048 uint4 per tile
    #pragma unroll
    for (int i = 0; i < 8; i++) {
        const int idx = i * 256 + tid;
        const int r = idx >> 4, c16 = idx & 15;
        uint4 v = *reinterpret_cast<uint4*>(Cs + r * CST + c16 * 8);
        *reinterpret_cast<uint4*>(g_K + (size_t)(by * 128 + r) * N + bx * 128 + c16 * 8) = v;
    }
}

// ---------------------------------------------------------------------------
// y = 1 / (K @ x).  RPB=10 rows/block, grid 820 <= capacity 888 (single wave).
// x cached in two 16KB smem halves. rev flips the column sweep direction per
// launch so consecutive passes re-read the most-recently-cached L2 data.
// ---------------------------------------------------------------------------
#define RPB 10
#define MV_GRID ((N + RPB - 1) / RPB)   // 820

__global__ void __launch_bounds__(256, 6) matvec_kernel(int dir, int rev) {
    const float* __restrict__ x = dir ? g_v : g_u;
    float* __restrict__ y = dir ? g_u : g_v;

    __shared__ float xs[4096];           // 16 KB: one half of x
    __shared__ float red[RPB][8];

    const int tid = threadIdx.x;
    const int row0 = blockIdx.x * RPB;

    float acc[RPB];
    #pragma unroll
    for (int r = 0; r < RPB; r++) acc[r] = 0.0f;

    #pragma unroll
    for (int hh = 0; hh < 2; hh++) {
        const int h = rev ? (1 - hh) : hh;
        #pragma unroll
        for (int i = 0; i < 4; i++)
            reinterpret_cast<float4*>(xs)[i * 256 + tid] =
                reinterpret_cast<const float4*>(x)[h * 1024 + i * 256 + tid];
        __syncthreads();

        #pragma unroll
        for (int ii = 0; ii < 2; ii++) {
            const int it = rev ? (1 - ii) : ii;
            const int j = h * 512 + it * 256 + tid;      // uint4 column index
            float xf[8];
            *reinterpret_cast<float4*>(&xf[0]) = *reinterpret_cast<float4*>(&xs[(it * 256 + tid) * 8]);
            *reinterpret_cast<float4*>(&xf[4]) = *reinterpret_cast<float4*>(&xs[(it * 256 + tid) * 8 + 4]);
            #pragma unroll
            for (int rb = 0; rb < 2; rb++) {
                uint4 raw[5];
                #pragma unroll
                for (int r = 0; r < 5; r++) {
                    int row = row0 + rb * 5 + r;
                    if (row > N - 1) row = N - 1;        // clamp (last block only)
                    raw[r] = reinterpret_cast<const uint4*>(g_K + (size_t)row * N)[j];
                }
                #pragma unroll
                for (int r = 0; r < 5; r++) {
                    const __half2* h2 = reinterpret_cast<const __half2*>(&raw[r]);
                    #pragma unroll
                    for (int e = 0; e < 4; e++) {
                        float2 kk = __half22float2(h2[e]);
                        acc[rb * 5 + r] += kk.x * xf[2 * e] + kk.y * xf[2 * e + 1];
                    }
                }
            }
        }
        __syncthreads();
    }

    const int lane = tid & 31, wd = tid >> 5;
    #pragma unroll
    for (int r = 0; r < RPB; r++) {
        float a = acc[r];
        #pragma unroll
        for (int o = 16; o > 0; o >>= 1) a += __shfl_xor_sync(0xffffffffu, a, o);
        if (lane == 0) red[r][wd] = a;
    }
    __syncthreads();
    if (tid < RPB) {
        float total = 0.0f;
        #pragma unroll
        for (int w = 0; w < 8; w++) total += red[tid][w];
        const int row = row0 + tid;
        if (row < N) y[row] = 1.0f / total;
    }
}

// ---------------------------------------------------------------------------
// Fused last matvec + loss row-partials (same structure, rev sweep).
//   s_i = sum_j K_ij v_j,  t_i = sum_j K_ij v_j * C_ij,  C_ij = -EPS*ln(K_ij)
// ---------------------------------------------------------------------------
__global__ void __launch_bounds__(256, 6) final_kernel(int rev) {
    __shared__ float xs[4096];
    __shared__ float reds[RPB][8], redt[RPB][8];

    const int tid = threadIdx.x;
    const int row0 = blockIdx.x * RPB;

    float s[RPB], t[RPB];
    #pragma unroll
    for (int r = 0; r < RPB; r++) { s[r] = 0.0f; t[r] = 0.0f; }

    #pragma unroll
    for (int hh = 0; hh < 2; hh++) {
        const int h = rev ? (1 - hh) : hh;
        #pragma unroll
        for (int i = 0; i < 4; i++)
            reinterpret_cast<float4*>(xs)[i * 256 + tid] =
                reinterpret_cast<const float4*>(g_v)[h * 1024 + i * 256 + tid];
        __syncthreads();

        #pragma unroll
        for (int ii = 0; ii < 2; ii++) {
            const int it = rev ? (1 - ii) : ii;
            const int j = h * 512 + it * 256 + tid;
            float xf[8];
            *reinterpret_cast<float4*>(&xf[0]) = *reinterpret_cast<float4*>(&xs[(it * 256 + tid) * 8]);
            *reinterpret_cast<float4*>(&xf[4]) = *reinterpret_cast<float4*>(&xs[(it * 256 + tid) * 8 + 4]);
            #pragma unroll
            for (int rb = 0; rb < 2; rb++) {
                uint4 raw[5];
                #pragma unroll
                for (int r = 0; r < 5; r++) {
                    int row = row0 + rb * 5 + r;
                    if (row > N - 1) row = N - 1;
                    raw[r] = reinterpret_cast<const uint4*>(g_K + (size_t)row * N)[j];
                }
                #pragma unroll
                for (int r = 0; r < 5; r++) {
                    const __half2* h2 = reinterpret_cast<const __half2*>(&raw[r]);
                    #pragma unroll
                    for (int e = 0; e < 4; e++) {
                        float2 kk = __half22float2(h2[e]);
                        float kv0 = kk.x * xf[2 * e];
                        float kv1 = kk.y * xf[2 * e + 1];
                        s[rb * 5 + r] += kv0 + kv1;
                        t[rb * 5 + r] += kv0 * (-EPS * __logf(fmaxf(kk.x, 1e-30f)))
                                       + kv1 * (-EPS * __logf(fmaxf(kk.y, 1e-30f)));
                    }
                }
            }
        }
        __syncthreads();
    }

    const int lane = tid & 31, wd = tid >> 5;
    #pragma unroll
    for (int r = 0; r < RPB; r++) {
        float a = s[r], b = t[r];
        #pragma unroll
        for (int o = 16; o > 0; o >>= 1) {
            a += __shfl_xor_sync(0xffffffffu, a, o);
            b += __shfl_xor_sync(0xffffffffu, b, o);
        }
        if (lane == 0) { reds[r][wd] = a; redt[r][wd] = b; }
    }
    __syncthreads();
    if (tid < RPB) {
        float st = 0.0f, tt = 0.0f;
        #pragma unroll
        for (int w = 0; w < 8; w++) { st += reds[tid][w]; tt += redt[tid][w]; }
        const int row = row0 + tid;
        if (row < N) g_part[row] = tt / st;
    }
}

__global__ void sum_kernel(float* __restrict__ out) {
    float a = 0.0f;
    for (int i = threadIdx.x; i < N; i += 1024) a += g_part[i];
    __shared__ float sm[32];
    #pragma unroll
    for (int o = 16; o > 0; o >>= 1) a += __shfl_xor_sync(0xffffffffu, a, o);
    if ((threadIdx.x & 31) == 0) sm[threadIdx.x >> 5] = a;
    __syncthreads();
    if (threadIdx.x == 0) {
        float total = 0.0f;
        #pragma unroll
        for (int w = 0; w < 32; w++) total += sm[w];
        out[0] = total;
    }
}

// ---------------------------------------------------------------------------
extern "C" void kernel_launch(void* const* d_in, const int* in_sizes, int n_in,
                              void* d_out, int out_size) {
    (void)in_sizes; (void)n_in; (void)out_size;
    const float* P = (const float*)d_in[0];
    const float* Q = (const float*)d_in[1];
    float* out = (float*)d_out;

    norms_kernel<<<N / 8, 256>>>(P, Q);
    build_kernel<<<dim3(N / 128, N / 128), 256>>>(P, Q);

    // 9 matvecs: alternate column sweep direction for L2 reuse
    int li = 0;
    for (int it = 0; it < 5; it++) {
        matvec_kernel<<<MV_GRID, 256>>>(0, li & 1); li++;        // v = 1/(K u)
        if (it < 4) { matvec_kernel<<<MV_GRID, 256>>>(1, li & 1); li++; }  // u = 1/(K v)
    }
    final_kernel<<<MV_GRID, 256>>>(li & 1);                       // fused 10th matvec
    sum_kernel<<<1, 1024>>>(out);
}